// round 17
// baseline (speedup 1.0000x reference)
#include <cuda_runtime.h>

// ---------------------------------------------------------------------------
// Grid-accelerated exact NN (chamfer forward, masked mean).
// pc1: 64^3 grid (h=0.125) with occupancy bitmasks (R9-proven setup).
// pc0: 32^3 supercells (0.25). Search: ONE WARP PER SUPERCELL, queries
// one-per-lane, candidates from the 4x4x4 h-cell ring streamed ONCE as
// broadcast loads (10x fewer load instrs than per-query gathering).
// Certify at h^2; uncertified lanes fall back to per-thread shells r=2..12.
// Final reduction fused into search via done-counter.
// ---------------------------------------------------------------------------

#define NPTS 65536
#define GD   64
#define NC   (GD * GD * GD)
#define SG   32
#define NSC  (SG * SG * SG)          // 32768 supercells
#define H    0.125f
#define INVH 8.0f
#define INVHS 4.0f
#define GOFF 4.0f
#define ST   256
#define SB   (NSC / 8)               // 4096 blocks, 8 warps = 8 supercells

typedef unsigned long long u64;

// Scratch (no allocations -> __device__ globals)
__device__ int    g_count [NC];      // pc1 grid
__device__ int    g_off   [NC + 1];
__device__ int    g_cursor[NC];
__device__ int    g_count0 [NSC];    // pc0 supercell grid
__device__ int    g_off0   [NSC + 1];
__device__ int    g_cursor0[NSC];
__device__ int    g_bsum  [2][256];
__device__ u64    g_occ [GD * GD];   // per (z,y) row: occupied x bits (pc1)
__device__ u64    g_occX[GD * GD];   // per (z,x) column: occupied y bits (pc1)
__device__ u64    g_occP[GD];        // per z plane: nonempty-row y bits
__device__ float4 g_pts [NPTS];      // sorted pc1: (x,y,z,||b||^2)
__device__ float4 g_pts0[NPTS];      // sorted pc0: (x,y,z,||a||^2)
__device__ float  g_block[SB * 2];   // per-block (sum, count)
__device__ int    g_done;            // search completion counter

__device__ __forceinline__ int cellc(float v) {
    int c = (int)floorf((v + GOFF) * INVH);
    return min(GD - 1, max(0, c));
}
__device__ __forceinline__ int cellc0(float v) {
    int c = (int)floorf((v + GOFF) * INVHS);
    return min(SG - 1, max(0, c));
}
__device__ __forceinline__ u64 bitrange(int lo, int hi) {
    return (~0ull << lo) & (~0ull >> (63 - hi));
}

// ---------------------------------------------------------------------------
__global__ void zero_k() {
    int i = blockIdx.x * blockDim.x + threadIdx.x;
    if (i < NC) g_count[i] = 0;
    if (i < NSC) g_count0[i] = 0;
    if (i < GD * GD) { g_occ[i] = 0; g_occX[i] = 0; }
    if (i < GD) g_occP[i] = 0;
    if (i == 0) g_done = 0;
}

__global__ void count_k(const float* __restrict__ pc1,
                        const float* __restrict__ pc0) {
    int i = blockIdx.x * blockDim.x + threadIdx.x;
    {
        float x = pc1[3 * i], y = pc1[3 * i + 1], z = pc1[3 * i + 2];
        int cx = cellc(x), cy = cellc(y), cz = cellc(z);
        atomicAdd(&g_count[(cz * GD + cy) * GD + cx], 1);
        atomicOr(&g_occ [cz * GD + cy], 1ull << cx);
        atomicOr(&g_occX[cz * GD + cx], 1ull << cy);
    }
    {
        float x = pc0[3 * i], y = pc0[3 * i + 1], z = pc0[3 * i + 2];
        atomicAdd(&g_count0[(cellc0(z) * SG + cellc0(y)) * SG + cellc0(x)], 1);
    }
}

// --- 3-phase exclusive scan: which=0 -> 256 tiles (pc1), which=1 -> 32 tiles
__global__ void scan_a() {
    int which = blockIdx.y;
    if (which == 1 && blockIdx.x >= 32) return;
    int* cnt = which ? g_count0 : g_count;
    int t = threadIdx.x;
    int base = (blockIdx.x * 256 + t) * 4;
    int s = cnt[base] + cnt[base + 1] + cnt[base + 2] + cnt[base + 3];
    __shared__ int sh[256];
    sh[t] = s; __syncthreads();
    for (int o = 1; o < 256; o <<= 1) {
        int u = (t >= o) ? sh[t - o] : 0; __syncthreads();
        sh[t] += u; __syncthreads();
    }
    if (t == 255) g_bsum[which][blockIdx.x] = sh[255];
}

// blocks 0,1: block-sum scans (stale entries past tile count are never read);
// block 2: build g_occP from g_occ
__global__ void scan_b() {
    int t = threadIdx.x;
    if (blockIdx.x == 2) {
        int z = t >> 2, q = t & 3;
        u64 w = 0;
        for (int y = q * 16; y < q * 16 + 16; y++)
            if (g_occ[z * GD + y]) w |= 1ull << y;
        if (w) atomicOr(&g_occP[z], w);
        return;
    }
    int which = blockIdx.x;
    __shared__ int sh[256];
    int v = g_bsum[which][t];
    sh[t] = v; __syncthreads();
    for (int o = 1; o < 256; o <<= 1) {
        int u = (t >= o) ? sh[t - o] : 0; __syncthreads();
        sh[t] += u; __syncthreads();
    }
    g_bsum[which][t] = sh[t] - v;
}

__global__ void scan_c() {
    int which = blockIdx.y;
    if (which == 1 && blockIdx.x >= 32) return;
    int* cnt = which ? g_count0  : g_count;
    int* off = which ? g_off0    : g_off;
    int* cur = which ? g_cursor0 : g_cursor;
    int t = threadIdx.x;
    int base = (blockIdx.x * 256 + t) * 4;
    int c0 = cnt[base], c1 = cnt[base + 1];
    int c2 = cnt[base + 2], c3 = cnt[base + 3];
    int s = c0 + c1 + c2 + c3;
    __shared__ int sh[256];
    sh[t] = s; __syncthreads();
    for (int o = 1; o < 256; o <<= 1) {
        int u = (t >= o) ? sh[t - o] : 0; __syncthreads();
        sh[t] += u; __syncthreads();
    }
    int o0 = sh[t] - s + g_bsum[which][blockIdx.x];
    int o1 = o0 + c0, o2 = o1 + c1, o3 = o2 + c2;
    off[base] = o0;     off[base + 1] = o1;
    off[base + 2] = o2; off[base + 3] = o3;
    cur[base] = o0;     cur[base + 1] = o1;
    cur[base + 2] = o2; cur[base + 3] = o3;
    if (blockIdx.x == 0 && t == 0) off[which ? NSC : NC] = NPTS;
}

__global__ void scatter_k(const float* __restrict__ pc1,
                          const float* __restrict__ pc0) {
    int i = blockIdx.x * blockDim.x + threadIdx.x;
    {
        float x = pc1[3 * i], y = pc1[3 * i + 1], z = pc1[3 * i + 2];
        int c = (cellc(z) * GD + cellc(y)) * GD + cellc(x);
        int idx = atomicAdd(&g_cursor[c], 1);
        g_pts[idx] = make_float4(x, y, z, x * x + y * y + z * z);
    }
    {
        float x = pc0[3 * i], y = pc0[3 * i + 1], z = pc0[3 * i + 2];
        int c = (cellc0(z) * SG + cellc0(y)) * SG + cellc0(x);
        int idx = atomicAdd(&g_cursor0[c], 1);
        g_pts0[idx] = make_float4(x, y, z, fmaf(x, x, fmaf(y, y, z * z)));
    }
}

// ---------------------------------------------------------------------------
// Search: one warp per supercell. Queries one-per-lane; candidates from the
// supercell's 4x4x4 h-cell ring streamed once (warp-uniform broadcast loads).
// Certify at h^2 (ring guarantees unscanned d >= h^2). Uncertified lanes run
// per-thread shell expansion r=2..12, seeded with the phase-1 min.
// ---------------------------------------------------------------------------
__global__ void __launch_bounds__(ST) search_k(float* __restrict__ out) {
    int t = threadIdx.x;
    int lane = t & 31;
    int sc = blockIdx.x * 8 + (t >> 5);      // one supercell per warp

    float ssum = 0.f, scnt = 0.f;

    int q_s = __ldg(&g_off0[sc]);
    int q_e = __ldg(&g_off0[sc + 1]);
    if (q_e > q_s) {
        int sx = sc & (SG - 1), sy = (sc >> 5) & (SG - 1), sz = sc >> 10;
        int x0 = max(2 * sx - 1, 0), x1 = min(2 * sx + 2, GD - 1);
        int y0 = max(2 * sy - 1, 0), y1 = min(2 * sy + 2, GD - 1);
        int z0 = max(2 * sz - 1, 0), z1 = min(2 * sz + 2, GD - 1);
        u64 xm = bitrange(x0, x1);

        for (int qb = q_s; qb < q_e; qb += 32) {
            int qi = qb + lane;
            bool valid = qi < q_e;
            float4 a = valid ? __ldg(&g_pts0[qi]) : make_float4(0.f, 0.f, 0.f, 1e30f);
            float nax = -2.f * a.x, nay = -2.f * a.y, naz = -2.f * a.z;
            float asq = a.w;

            float m = 1e30f, m2 = 1e30f;
            // stream the ring: warp-uniform rows, broadcast candidate loads
            for (int z = z0; z <= z1; z++) {
                int zb = z * GD;
                for (int y = y0; y <= y1; y++) {
                    u64 w = __ldg(&g_occ[zb + y]) & xm;
                    if (w) {
                        int lo = __ffsll((long long)w) - 1;
                        int hi = 63 - __clzll(w);
                        int s = __ldg(&g_off[(zb + y) * GD + lo]);
                        int e = __ldg(&g_off[(zb + y) * GD + hi + 1]);
                        int k = s;
                        for (; k + 1 < e; k += 2) {
                            float4 p0 = __ldg(&g_pts[k]);
                            float4 p1 = __ldg(&g_pts[k + 1]);
                            m  = fminf(m,  fmaf(nax, p0.x, fmaf(nay, p0.y, fmaf(naz, p0.z, p0.w))));
                            m2 = fminf(m2, fmaf(nax, p1.x, fmaf(nay, p1.y, fmaf(naz, p1.z, p1.w))));
                        }
                        if (k < e) {
                            float4 p = __ldg(&g_pts[k]);
                            m = fminf(m, fmaf(nax, p.x, fmaf(nay, p.y, fmaf(naz, p.z, p.w))));
                        }
                    }
                }
            }
            m = fminf(m, m2);

            // fallback for uncertified valid lanes (per-thread shells)
            if (valid && !(m + asq <= H * H)) {
                int cx = cellc(a.x), cy = cellc(a.y), cz = cellc(a.z);
                for (int r = 2; r <= 12; r++) {
                    int zz0 = max(cz - r, 0), zz1 = min(cz + r, GD - 1);
                    int yy0 = max(cy - r, 0), yy1 = min(cy + r, GD - 1);
                    int xl = cx - r, xr = cx + r;
                    int xx0 = max(xl, 0), xx1 = min(xr, GD - 1);
                    u64 xmr = bitrange(xx0, xx1);
                    for (int z = zz0; z <= zz1; z++) {
                        int zb = z * GD;
                        bool zedge = (z == cz - r) || (z == cz + r);
                        if (zedge) {
                            u64 wp = __ldg(&g_occP[z]) & bitrange(yy0, yy1);
                            while (wp) {
                                int y = __ffsll((long long)wp) - 1; wp &= wp - 1;
                                u64 w = __ldg(&g_occ[zb + y]) & xmr;
                                if (w) {
                                    int lo = __ffsll((long long)w) - 1;
                                    int hi = 63 - __clzll(w);
                                    int s = __ldg(&g_off[(zb + y) * GD + lo]);
                                    int e = __ldg(&g_off[(zb + y) * GD + hi + 1]);
                                    for (int k = s; k < e; k++) {
                                        float4 p = __ldg(&g_pts[k]);
                                        m = fminf(m, fmaf(nax, p.x, fmaf(nay, p.y, fmaf(naz, p.z, p.w))));
                                    }
                                }
                            }
                        } else {
                            int yl = cy - r, yr2 = cy + r;
                            if (yl >= 0) {
                                u64 w = __ldg(&g_occ[zb + yl]) & xmr;
                                if (w) {
                                    int lo = __ffsll((long long)w) - 1;
                                    int hi = 63 - __clzll(w);
                                    int s = __ldg(&g_off[(zb + yl) * GD + lo]);
                                    int e = __ldg(&g_off[(zb + yl) * GD + hi + 1]);
                                    for (int k = s; k < e; k++) {
                                        float4 p = __ldg(&g_pts[k]);
                                        m = fminf(m, fmaf(nax, p.x, fmaf(nay, p.y, fmaf(naz, p.z, p.w))));
                                    }
                                }
                            }
                            if (yr2 <= GD - 1) {
                                u64 w = __ldg(&g_occ[zb + yr2]) & xmr;
                                if (w) {
                                    int lo = __ffsll((long long)w) - 1;
                                    int hi = 63 - __clzll(w);
                                    int s = __ldg(&g_off[(zb + yr2) * GD + lo]);
                                    int e = __ldg(&g_off[(zb + yr2) * GD + hi + 1]);
                                    for (int k = s; k < e; k++) {
                                        float4 p = __ldg(&g_pts[k]);
                                        m = fminf(m, fmaf(nax, p.x, fmaf(nay, p.y, fmaf(naz, p.z, p.w))));
                                    }
                                }
                            }
                            int yi0 = max(yl + 1, 0), yi1 = min(yr2 - 1, GD - 1);
                            if (yi0 <= yi1) {
                                u64 ym = bitrange(yi0, yi1);
                                if (xl >= 0) {
                                    u64 wc = __ldg(&g_occX[zb + xl]) & ym;
                                    while (wc) {
                                        int y = __ffsll((long long)wc) - 1; wc &= wc - 1;
                                        int c = (zb + y) * GD + xl;
                                        int s = __ldg(&g_off[c]);
                                        int e = __ldg(&g_off[c + 1]);
                                        for (int k = s; k < e; k++) {
                                            float4 p = __ldg(&g_pts[k]);
                                            m = fminf(m, fmaf(nax, p.x, fmaf(nay, p.y, fmaf(naz, p.z, p.w))));
                                        }
                                    }
                                }
                                if (xr <= GD - 1) {
                                    u64 wc = __ldg(&g_occX[zb + xr]) & ym;
                                    while (wc) {
                                        int y = __ffsll((long long)wc) - 1; wc &= wc - 1;
                                        int c = (zb + y) * GD + xr;
                                        int s = __ldg(&g_off[c]);
                                        int e = __ldg(&g_off[c + 1]);
                                        for (int k = s; k < e; k++) {
                                            float4 p = __ldg(&g_pts[k]);
                                            m = fminf(m, fmaf(nax, p.x, fmaf(nay, p.y, fmaf(naz, p.z, p.w))));
                                        }
                                    }
                                }
                            }
                        }
                    }
                    float rh = r * H;
                    float rh2 = rh * rh;
                    if (m + asq <= rh2 || rh2 > 2.0f) break;
                }
            }

            if (valid) {
                float d = m + asq;
                if (d <= 2.0f) { ssum += d; scnt += 1.f; }
            }
        }
    }

    // warp sum (all lanes converged; fixed lane order)
    for (int o = 16; o; o >>= 1) {
        ssum += __shfl_xor_sync(0xFFFFFFFFu, ssum, o);
        scnt += __shfl_xor_sync(0xFFFFFFFFu, scnt, o);
    }
    __shared__ float ws[8], wc2[8];
    if (lane == 0) { ws[t >> 5] = ssum; wc2[t >> 5] = scnt; }
    __syncthreads();
    __shared__ int isLast;
    if (t == 0) {
        float bs = 0.f, bc = 0.f;
#pragma unroll
        for (int w = 0; w < 8; w++) { bs += ws[w]; bc += wc2[w]; }
        g_block[2 * blockIdx.x + 0] = bs;
        g_block[2 * blockIdx.x + 1] = bc;
        __threadfence();
        isLast = (atomicAdd(&g_done, 1) == SB - 1);
    }
    __syncthreads();
    if (isLast) {
        __shared__ float fs_[ST], fc_[ST];
        float fs = 0.f, fc = 0.f;
        for (int k = t; k < SB; k += ST) {
            fs += g_block[2 * k + 0];
            fc += g_block[2 * k + 1];
        }
        fs_[t] = fs; fc_[t] = fc;
        __syncthreads();
        for (int o = ST / 2; o > 0; o >>= 1) {
            if (t < o) { fs_[t] += fs_[t + o]; fc_[t] += fc_[t + o]; }
            __syncthreads();
        }
        if (t == 0) out[0] = fs_[0] / fc_[0];
    }
}

extern "C" void kernel_launch(void* const* d_in, const int* in_sizes, int n_in,
                              void* d_out, int out_size) {
    const float* pc0 = (const float*)d_in[0];
    const float* pc1 = (const float*)d_in[1];
    (void)in_sizes; (void)n_in; (void)out_size;

    zero_k   <<<NC / 256, 256>>>();
    count_k  <<<NPTS / 256, 256>>>(pc1, pc0);
    scan_a   <<<dim3(256, 2), 256>>>();
    scan_b   <<<3, 256>>>();
    scan_c   <<<dim3(256, 2), 256>>>();
    scatter_k<<<NPTS / 256, 256>>>(pc1, pc0);
    search_k <<<SB, ST>>>((float*)d_out);
}